// round 2
// baseline (speedup 1.0000x reference)
#include <cuda_runtime.h>

#define TOK  4096
#define Dm   1024
#define Sdim 16
#define Edim 4
#define Hdim 2048
#define Ldim 2048
#define NCH  32      // scan chunks
#define CH   64      // chunk length (NCH*CH = Ldim)

// ---------------- scratch (device globals; no allocation) ----------------
__device__ float g_delta[(size_t)TOK * Dm];              // 16 MB
__device__ float g_Bm[(size_t)TOK * Sdim];
__device__ float g_Cm[(size_t)TOK * Sdim];
__device__ float g_ssm[(size_t)TOK * Dm];                // 16 MB
__device__ float g_hidden[(size_t)Edim * TOK * Hdim];    // 128 MB
__device__ float g_expout[(size_t)Edim * TOK * Dm];      // 64 MB
__device__ float g_hp[(size_t)2 * Dm * NCH * Sdim];      // 4 MB  partial h
__device__ float g_ap[(size_t)2 * Dm * NCH * Sdim];      // 4 MB  A products
__device__ float g_hi[(size_t)2 * Dm * NCH * Sdim];      // 4 MB  chunk h_init
__device__ int   g_cnt[Edim];
__device__ int   g_idx[Edim * TOK];
__device__ int   g_tokexp[2 * TOK];
__device__ int   g_tokslot[2 * TOK];
__device__ float g_tokw[2 * TOK];

// ---------------- f32x2 helpers ----------------
static __device__ __forceinline__ void ffma2(unsigned long long& c,
                                             unsigned long long a,
                                             unsigned long long b) {
    asm("fma.rn.f32x2 %0, %1, %2, %0;" : "+l"(c) : "l"(a), "l"(b));
}
union F4U { float4 f4; float f[4]; unsigned long long u2[2]; };

// ---------------- init ----------------
__global__ void k_init() {
    if (threadIdx.x < Edim) g_cnt[threadIdx.x] = 0;
}

// ============== GEMM (modes 0 and 3), 128x128x8, dup-A smem ==============
// MODE 0: g_delta = softplus(x @ W_delta + b_delta)     (M=TOK, N=Dm, K=Dm)
// MODE 3: g_expout[e] = g_hidden[e] @ Wd[e]             (M=cnt[e], N=Dm, K=Hdim)
template <int MODE>
__global__ __launch_bounds__(256, 2)
void k_gemm(const float* __restrict__ Aext, const float* __restrict__ Bext,
            const float* __restrict__ bias) {
    constexpr int N = Dm;
    constexpr int K = (MODE == 3) ? Hdim : Dm;
    const int e = blockIdx.z;

    const float* A; const float* B; int M;
    if (MODE == 0) { A = Aext;                           B = Bext;                     M = TOK; }
    else           { A = g_hidden + (size_t)e * TOK * K; B = Bext + (size_t)e * K * N; M = g_cnt[e]; }

    const int m0 = blockIdx.y * 128;
    const int n0 = blockIdx.x * 128;
    if (m0 >= M) return;

    __shared__ __align__(16) float2 As2[8][128];
    __shared__ __align__(16) float  Bs[8][128];

    const int tid  = threadIdx.x;
    const int arow = tid >> 1;
    const int acol = (tid & 1) * 4;
    const int brow = tid >> 5;
    const int bcol = (tid & 31) * 4;
    const int tx = tid & 15, ty = tid >> 4;

    const bool avalid = (m0 + arow) < M;
    const float* aptr = A + (size_t)(m0 + arow) * K + acol;
    const float* bptr = B + (size_t)brow * N + n0 + bcol;

    float4 a_ld = avalid ? *(const float4*)aptr : make_float4(0.f, 0.f, 0.f, 0.f);
    float4 b_ld = *(const float4*)bptr;

    unsigned long long acc[8][4];
#pragma unroll
    for (int i = 0; i < 8; i++)
#pragma unroll
        for (int j = 0; j < 4; j++) acc[i][j] = 0ULL;

    const int KT = K / 8;
    for (int kt = 0; kt < KT; kt++) {
        As2[acol + 0][arow] = make_float2(a_ld.x, a_ld.x);
        As2[acol + 1][arow] = make_float2(a_ld.y, a_ld.y);
        As2[acol + 2][arow] = make_float2(a_ld.z, a_ld.z);
        As2[acol + 3][arow] = make_float2(a_ld.w, a_ld.w);
        *(float4*)&Bs[brow][bcol] = b_ld;
        __syncthreads();

        if (kt + 1 < KT) {
            a_ld = avalid ? *(const float4*)(aptr + (size_t)(kt + 1) * 8)
                          : make_float4(0.f, 0.f, 0.f, 0.f);
            b_ld = *(const float4*)(bptr + (size_t)(kt + 1) * 8 * N);
        }

#pragma unroll
        for (int k = 0; k < 8; k++) {
            F4U a01, a23, a45, a67, b0, b1;
            a01.f4 = *(const float4*)&As2[k][ty * 4 + 0];
            a23.f4 = *(const float4*)&As2[k][ty * 4 + 2];
            a45.f4 = *(const float4*)&As2[k][64 + ty * 4 + 0];
            a67.f4 = *(const float4*)&As2[k][64 + ty * 4 + 2];
            b0.f4 = *(const float4*)&Bs[k][tx * 4];
            b1.f4 = *(const float4*)&Bs[k][64 + tx * 4];
            unsigned long long ad[8] = {a01.u2[0], a01.u2[1], a23.u2[0], a23.u2[1],
                                        a45.u2[0], a45.u2[1], a67.u2[0], a67.u2[1]};
            unsigned long long bb[4] = {b0.u2[0], b0.u2[1], b1.u2[0], b1.u2[1]};
#pragma unroll
            for (int i = 0; i < 8; i++) {
                ffma2(acc[i][0], ad[i], bb[0]);
                ffma2(acc[i][1], ad[i], bb[1]);
                ffma2(acc[i][2], ad[i], bb[2]);
                ffma2(acc[i][3], ad[i], bb[3]);
            }
        }
        __syncthreads();
    }

#pragma unroll
    for (int i = 0; i < 8; i++) {
        int rloc = (i < 4) ? (ty * 4 + i) : (64 + ty * 4 + (i - 4));
        int r = m0 + rloc;
        if (MODE != 0 && r >= M) continue;
        F4U lo, hi;
        lo.u2[0] = acc[i][0]; lo.u2[1] = acc[i][1];
        hi.u2[0] = acc[i][2]; hi.u2[1] = acc[i][3];
        int c0 = n0 + tx * 4;
        int c1 = n0 + 64 + tx * 4;
        if (MODE == 0) {
            F4U o0, o1;
#pragma unroll
            for (int j = 0; j < 4; j++) {
                float v0 = lo.f[j] + bias[c0 + j];
                float v1 = hi.f[j] + bias[c1 + j];
                o0.f[j] = v0 > 20.f ? v0 : log1pf(__expf(v0));
                o1.f[j] = v1 > 20.f ? v1 : log1pf(__expf(v1));
            }
            *(float4*)&g_delta[(size_t)r * N + c0] = o0.f4;
            *(float4*)&g_delta[(size_t)r * N + c1] = o1.f4;
        } else {
            float* O = g_expout + ((size_t)e * TOK + r) * N;
            *(float4*)&O[c0] = lo.f4;
            *(float4*)&O[c1] = hi.f4;
        }
    }
}

// ============== fused Wg/Wu GEMM: hidden = silu(A@Wg) * (A@Wu) =============
// 128 rows x 64 cols per block, both products from one A tile.
__global__ __launch_bounds__(256, 2)
void k_gemm12(const float* __restrict__ Wg, const float* __restrict__ Wu) {
    constexpr int N = Hdim;
    constexpr int K = Dm;
    const int e = blockIdx.z;
    const int M = g_cnt[e];
    const int m0 = blockIdx.y * 128;
    const int n0 = blockIdx.x * 64;
    if (m0 >= M) return;

    __shared__ __align__(16) float2 As2[8][128];
    __shared__ __align__(16) float  Bsg[8][64];
    __shared__ __align__(16) float  Bsu[8][64];

    const int tid  = threadIdx.x;
    const int arow = tid >> 1;
    const int acol = (tid & 1) * 4;
    const int brow = tid >> 5;
    const int bcol = (tid & 31) * 2;
    const int tx = tid & 15, ty = tid >> 4;

    const int mr = m0 + arow;
    const bool avalid = mr < M;
    const int gr = avalid ? g_idx[e * TOK + mr] : 0;
    const float* aptr = g_ssm + (size_t)gr * K + acol;
    const float* gptr = Wg + (size_t)e * K * N + (size_t)brow * N + n0 + bcol;
    const float* uptr = Wu + (size_t)e * K * N + (size_t)brow * N + n0 + bcol;

    float4 a_ld = avalid ? *(const float4*)aptr : make_float4(0.f, 0.f, 0.f, 0.f);
    float2 g_ld = *(const float2*)gptr;
    float2 u_ld = *(const float2*)uptr;

    unsigned long long accg[8][2], accu[8][2];
#pragma unroll
    for (int i = 0; i < 8; i++) {
        accg[i][0] = accg[i][1] = 0ULL;
        accu[i][0] = accu[i][1] = 0ULL;
    }

    const int KT = K / 8;
    for (int kt = 0; kt < KT; kt++) {
        As2[acol + 0][arow] = make_float2(a_ld.x, a_ld.x);
        As2[acol + 1][arow] = make_float2(a_ld.y, a_ld.y);
        As2[acol + 2][arow] = make_float2(a_ld.z, a_ld.z);
        As2[acol + 3][arow] = make_float2(a_ld.w, a_ld.w);
        *(float2*)&Bsg[brow][bcol] = g_ld;
        *(float2*)&Bsu[brow][bcol] = u_ld;
        __syncthreads();

        if (kt + 1 < KT) {
            a_ld = avalid ? *(const float4*)(aptr + (size_t)(kt + 1) * 8)
                          : make_float4(0.f, 0.f, 0.f, 0.f);
            g_ld = *(const float2*)(gptr + (size_t)(kt + 1) * 8 * N);
            u_ld = *(const float2*)(uptr + (size_t)(kt + 1) * 8 * N);
        }

#pragma unroll
        for (int k = 0; k < 8; k++) {
            F4U a01, a23, a45, a67, bg, bu;
            a01.f4 = *(const float4*)&As2[k][ty * 4 + 0];
            a23.f4 = *(const float4*)&As2[k][ty * 4 + 2];
            a45.f4 = *(const float4*)&As2[k][64 + ty * 4 + 0];
            a67.f4 = *(const float4*)&As2[k][64 + ty * 4 + 2];
            bg.f4 = *(const float4*)&Bsg[k][tx * 4];
            bu.f4 = *(const float4*)&Bsu[k][tx * 4];
            unsigned long long ad[8] = {a01.u2[0], a01.u2[1], a23.u2[0], a23.u2[1],
                                        a45.u2[0], a45.u2[1], a67.u2[0], a67.u2[1]};
#pragma unroll
            for (int i = 0; i < 8; i++) {
                ffma2(accg[i][0], ad[i], bg.u2[0]);
                ffma2(accg[i][1], ad[i], bg.u2[1]);
                ffma2(accu[i][0], ad[i], bu.u2[0]);
                ffma2(accu[i][1], ad[i], bu.u2[1]);
            }
        }
        __syncthreads();
    }

#pragma unroll
    for (int i = 0; i < 8; i++) {
        int rloc = (i < 4) ? (ty * 4 + i) : (64 + ty * 4 + (i - 4));
        int r = m0 + rloc;
        if (r >= M) continue;
        F4U gv, uv, ov;
        gv.u2[0] = accg[i][0]; gv.u2[1] = accg[i][1];
        uv.u2[0] = accu[i][0]; uv.u2[1] = accu[i][1];
#pragma unroll
        for (int j = 0; j < 4; j++) {
            float g = gv.f[j];
            ov.f[j] = (g / (1.f + __expf(-g))) * uv.f[j];
        }
        *(float4*)&g_hidden[((size_t)e * TOK + r) * Hdim + n0 + tx * 4] = ov.f4;
    }
}

// ---------------- Bm / Cm ----------------
__global__ void k_bc(const float* __restrict__ x, const float* __restrict__ WB,
                     const float* __restrict__ WC) {
    __shared__ float xs[Dm];
    __shared__ float red[8][32];
    int n = blockIdx.x, tid = threadIdx.x;
    const float* xr = x + (size_t)n * Dm;
    for (int i = tid; i < Dm; i += 256) xs[i] = xr[i];
    __syncthreads();
    int o = tid & 31, part = tid >> 5;
    const float* W = (o < 16) ? WB : WC;
    int s = o & 15;
    float acc = 0.f;
    int k0 = part * 128;
#pragma unroll 8
    for (int k = 0; k < 128; k++) acc = fmaf(xs[k0 + k], W[(k0 + k) * Sdim + s], acc);
    red[part][o] = acc;
    __syncthreads();
    if (tid < 32) {
        float a = 0.f;
#pragma unroll
        for (int p = 0; p < 8; p++) a += red[p][tid];
        if (tid < 16) g_Bm[n * Sdim + tid] = a;
        else          g_Cm[n * Sdim + (tid - 16)] = a;
    }
}

// ============== chunked scan ==============
// Pass A: per (b,d,chunk): run chunk from h=0, record partial h and prod(barA).
__global__ __launch_bounds__(256)
void k_scanA(const float* __restrict__ x, const float* __restrict__ A_log) {
    const int d = blockIdx.x * 256 + threadIdx.x;
    const int c = blockIdx.y;
    const int b = blockIdx.z;
    __shared__ float sB[CH * Sdim];
    const float* bb = g_Bm + ((size_t)b * Ldim + c * CH) * Sdim;
    for (int i = threadIdx.x; i < CH * Sdim; i += 256) sB[i] = bb[i];
    __syncthreads();

    float Av[16];
#pragma unroll
    for (int q = 0; q < 4; q++) {
        float4 al = *(const float4*)&A_log[d * Sdim + q * 4];
        Av[q*4+0] = -__expf(al.x); Av[q*4+1] = -__expf(al.y);
        Av[q*4+2] = -__expf(al.z); Av[q*4+3] = -__expf(al.w);
    }
    float h[16], ap[16];
#pragma unroll
    for (int s = 0; s < 16; s++) { h[s] = 0.f; ap[s] = 1.f; }

    const size_t base = ((size_t)b * Ldim + c * CH) * Dm + d;
    for (int t = 0; t < CH; t++) {
        float xt = x[base + (size_t)t * Dm];
        float dt = g_delta[base + (size_t)t * Dm];
        float4 B0 = *(const float4*)&sB[t * 16 + 0];
        float4 B1 = *(const float4*)&sB[t * 16 + 4];
        float4 B2 = *(const float4*)&sB[t * 16 + 8];
        float4 B3 = *(const float4*)&sB[t * 16 + 12];
        float Bv[16] = {B0.x,B0.y,B0.z,B0.w, B1.x,B1.y,B1.z,B1.w,
                        B2.x,B2.y,B2.z,B2.w, B3.x,B3.y,B3.z,B3.w};
#pragma unroll
        for (int s = 0; s < 16; s++) {
            float a = __expf(fminf(dt * Av[s], 10.f));
            float u = fminf(fmaxf(dt * Bv[s], -10.f), 10.f) * xt;
            h[s] = fmaf(a, h[s], u);
            ap[s] *= a;
        }
    }
    const size_t oi = (((size_t)b * Dm + d) * NCH + c) * Sdim;
#pragma unroll
    for (int q = 0; q < 4; q++) {
        *(float4*)&g_hp[oi + q * 4] = make_float4(h[q*4], h[q*4+1], h[q*4+2], h[q*4+3]);
        *(float4*)&g_ap[oi + q * 4] = make_float4(ap[q*4], ap[q*4+1], ap[q*4+2], ap[q*4+3]);
    }
}

// Pass B: per (b,d,s): sequentially combine chunks -> h_init per chunk.
__global__ void k_scanB() {
    int g = blockIdx.x * 256 + threadIdx.x;          // 0 .. 2*Dm*Sdim-1
    size_t base = (size_t)(g >> 4) * NCH * Sdim + (g & 15);
    float hi = 0.f;
    for (int c = 0; c < NCH; c++) {
        g_hi[base + (size_t)c * Sdim] = hi;
        hi = fmaf(g_ap[base + (size_t)c * Sdim], hi, g_hp[base + (size_t)c * Sdim]);
    }
}

// Pass C: per (b,d,chunk): re-run from h_init producing outputs.
__global__ __launch_bounds__(256)
void k_scanC(const float* __restrict__ x, const float* __restrict__ A_log,
             const float* __restrict__ Dp) {
    const int d = blockIdx.x * 256 + threadIdx.x;
    const int c = blockIdx.y;
    const int b = blockIdx.z;
    __shared__ float sB[CH * Sdim];
    __shared__ float sC[CH * Sdim];
    {
        const float* bb = g_Bm + ((size_t)b * Ldim + c * CH) * Sdim;
        const float* cc = g_Cm + ((size_t)b * Ldim + c * CH) * Sdim;
        for (int i = threadIdx.x; i < CH * Sdim; i += 256) { sB[i] = bb[i]; sC[i] = cc[i]; }
    }
    __syncthreads();

    float Av[16];
#pragma unroll
    for (int q = 0; q < 4; q++) {
        float4 al = *(const float4*)&A_log[d * Sdim + q * 4];
        Av[q*4+0] = -__expf(al.x); Av[q*4+1] = -__expf(al.y);
        Av[q*4+2] = -__expf(al.z); Av[q*4+3] = -__expf(al.w);
    }
    const float dpar = Dp[d];
    float h[16];
    const size_t hidx = (((size_t)b * Dm + d) * NCH + c) * Sdim;
#pragma unroll
    for (int q = 0; q < 4; q++) {
        float4 hv = *(const float4*)&g_hi[hidx + q * 4];
        h[q*4] = hv.x; h[q*4+1] = hv.y; h[q*4+2] = hv.z; h[q*4+3] = hv.w;
    }

    const size_t base = ((size_t)b * Ldim + c * CH) * Dm + d;
    for (int t = 0; t < CH; t++) {
        float xt = x[base + (size_t)t * Dm];
        float dt = g_delta[base + (size_t)t * Dm];
        float4 B0 = *(const float4*)&sB[t * 16 + 0];
        float4 B1 = *(const float4*)&sB[t * 16 + 4];
        float4 B2 = *(const float4*)&sB[t * 16 + 8];
        float4 B3 = *(const float4*)&sB[t * 16 + 12];
        float4 C0 = *(const float4*)&sC[t * 16 + 0];
        float4 C1 = *(const float4*)&sC[t * 16 + 4];
        float4 C2 = *(const float4*)&sC[t * 16 + 8];
        float4 C3 = *(const float4*)&sC[t * 16 + 12];
        float Bv[16] = {B0.x,B0.y,B0.z,B0.w, B1.x,B1.y,B1.z,B1.w,
                        B2.x,B2.y,B2.z,B2.w, B3.x,B3.y,B3.z,B3.w};
        float Cv[16] = {C0.x,C0.y,C0.z,C0.w, C1.x,C1.y,C1.z,C1.w,
                        C2.x,C2.y,C2.z,C2.w, C3.x,C3.y,C3.z,C3.w};
        float y = xt * dpar;
#pragma unroll
        for (int s = 0; s < 16; s++) {
            float a = __expf(fminf(dt * Av[s], 10.f));
            float u = fminf(fmaxf(dt * Bv[s], -10.f), 10.f) * xt;
            float hv = fmaf(a, h[s], u);
            hv = fminf(fmaxf(hv, -10000.f), 10000.f);
            h[s] = hv;
            y = fmaf(hv, Cv[s], y);
        }
        g_ssm[base + (size_t)t * Dm] = y;
    }
}

// ---------------- router: softmax over 4 logits, top-2, bucket tokens ------
__global__ void k_router(const float* __restrict__ Wr) {
    int gw = (blockIdx.x * blockDim.x + threadIdx.x) >> 5;   // token id
    int lane = threadIdx.x & 31;
    const float* xr = g_ssm + (size_t)gw * Dm;
    float a0 = 0, a1 = 0, a2 = 0, a3 = 0;
    for (int k = lane; k < Dm; k += 32) {
        float xv = xr[k];
        float4 w = *(const float4*)&Wr[k * 4];
        a0 = fmaf(xv, w.x, a0); a1 = fmaf(xv, w.y, a1);
        a2 = fmaf(xv, w.z, a2); a3 = fmaf(xv, w.w, a3);
    }
#pragma unroll
    for (int m = 16; m > 0; m >>= 1) {
        a0 += __shfl_xor_sync(~0u, a0, m);
        a1 += __shfl_xor_sync(~0u, a1, m);
        a2 += __shfl_xor_sync(~0u, a2, m);
        a3 += __shfl_xor_sync(~0u, a3, m);
    }
    if (lane == 0) {
        float l[4] = {a0, a1, a2, a3};
        float mx = fmaxf(fmaxf(l[0], l[1]), fmaxf(l[2], l[3]));
        float p[4]; float Z = 0.f;
#pragma unroll
        for (int q = 0; q < 4; q++) { p[q] = __expf(l[q] - mx); Z += p[q]; }
        float inv = 1.f / Z;
#pragma unroll
        for (int q = 0; q < 4; q++) p[q] *= inv;
        int i0 = 0;
#pragma unroll
        for (int q = 1; q < 4; q++) if (p[q] > p[i0]) i0 = q;
        int i1 = -1;
#pragma unroll
        for (int q = 0; q < 4; q++) if (q != i0 && (i1 < 0 || p[q] > p[i1])) i1 = q;
        float w0 = p[i0], w1 = p[i1];
        float den = w0 + w1 + 1e-9f;
        w0 /= den; w1 /= den;
        int pos0 = atomicAdd(&g_cnt[i0], 1);
        g_idx[i0 * TOK + pos0] = gw;
        int pos1 = atomicAdd(&g_cnt[i1], 1);
        g_idx[i1 * TOK + pos1] = gw;
        g_tokexp[2 * gw]     = i0; g_tokslot[2 * gw]     = pos0; g_tokw[2 * gw]     = w0;
        g_tokexp[2 * gw + 1] = i1; g_tokslot[2 * gw + 1] = pos1; g_tokw[2 * gw + 1] = w1;
    }
}

// ---------------- rmsnorm over hidden rows ----------------
__global__ void k_rmsg(const float* __restrict__ wn) {
    int e = blockIdx.y, i = blockIdx.x;
    if (i >= g_cnt[e]) return;
    float* row = g_hidden + ((size_t)e * TOK + i) * Hdim;
    __shared__ float red[8];
    int tid = threadIdx.x, lane = tid & 31, w = tid >> 5;
    float v[8];
    float ss = 0.f;
#pragma unroll
    for (int q = 0; q < 8; q++) { v[q] = row[tid + q * 256]; ss += v[q] * v[q]; }
#pragma unroll
    for (int m = 16; m > 0; m >>= 1) ss += __shfl_xor_sync(~0u, ss, m);
    if (lane == 0) red[w] = ss;
    __syncthreads();
    if (tid == 0) {
        float t = 0.f;
#pragma unroll
        for (int j = 0; j < 8; j++) t += red[j];
        red[0] = rsqrtf(t * (1.f / Hdim) + 1e-6f);
    }
    __syncthreads();
    float r = red[0];
#pragma unroll
    for (int q = 0; q < 8; q++) row[tid + q * 256] = wn[e * Hdim + tid + q * 256] * v[q] * r;
}

// ---------------- final: out = rmsnorm(ssm + w0*eo0 + w1*eo1, norm_w) -------
__global__ void k_final(const float* __restrict__ nw, float* __restrict__ out) {
    int n = blockIdx.x;
    int tid = threadIdx.x, lane = tid & 31, w = tid >> 5;
    __shared__ float red[8];
    const float* s = g_ssm + (size_t)n * Dm;
    int e0 = g_tokexp[2 * n], e1 = g_tokexp[2 * n + 1];
    int s0 = g_tokslot[2 * n], s1 = g_tokslot[2 * n + 1];
    float w0 = g_tokw[2 * n], w1 = g_tokw[2 * n + 1];
    const float* r0 = g_expout + ((size_t)e0 * TOK + s0) * Dm;
    const float* r1 = g_expout + ((size_t)e1 * TOK + s1) * Dm;
    float v[4];
    float ss = 0.f;
#pragma unroll
    for (int q = 0; q < 4; q++) {
        int i = tid + q * 256;
        float t = s[i] + w0 * r0[i] + w1 * r1[i];
        v[q] = t; ss += t * t;
    }
#pragma unroll
    for (int mm = 16; mm > 0; mm >>= 1) ss += __shfl_xor_sync(~0u, ss, mm);
    if (lane == 0) red[w] = ss;
    __syncthreads();
    if (tid == 0) {
        float t = 0.f;
#pragma unroll
        for (int j = 0; j < 8; j++) t += red[j];
        red[0] = rsqrtf(t * (1.f / Dm) + 1e-6f);
    }
    __syncthreads();
    float r = red[0];
#pragma unroll
    for (int q = 0; q < 4; q++)
        out[(size_t)n * Dm + tid + q * 256] = nw[tid + q * 256] * v[q] * r;
}

// ---------------- launch ----------------
extern "C" void kernel_launch(void* const* d_in, const int* in_sizes, int n_in,
                              void* d_out, int out_size) {
    const float* x        = (const float*)d_in[0];
    const float* A_log    = (const float*)d_in[1];
    const float* D_param  = (const float*)d_in[2];
    const float* W_delta  = (const float*)d_in[3];
    const float* b_delta  = (const float*)d_in[4];
    const float* W_B      = (const float*)d_in[5];
    const float* W_C      = (const float*)d_in[6];
    const float* W_router = (const float*)d_in[7];
    const float* Wg       = (const float*)d_in[8];
    const float* Wu       = (const float*)d_in[9];
    const float* Wd       = (const float*)d_in[10];
    const float* wn_exp   = (const float*)d_in[11];
    const float* norm_w   = (const float*)d_in[12];
    float* out = (float*)d_out;

    k_init<<<1, 32>>>();
    k_gemm<0><<<dim3(Dm / 128, TOK / 128, 1), 256>>>(x, W_delta, b_delta);
    k_bc<<<TOK, 256>>>(x, W_B, W_C);
    k_scanA<<<dim3(Dm / 256, NCH, 2), 256>>>(x, A_log);
    k_scanB<<<(2 * Dm * Sdim) / 256, 256>>>();
    k_scanC<<<dim3(Dm / 256, NCH, 2), 256>>>(x, A_log, D_param);
    k_router<<<TOK / 8, 256>>>(W_router);
    k_gemm12<<<dim3(Hdim / 64, TOK / 128, Edim), 256>>>(Wg, Wu);
    k_rmsg<<<dim3(TOK, Edim), 256>>>(wn_exp);
    k_gemm<3><<<dim3(Dm / 128, TOK / 128, Edim), 256>>>(nullptr, Wd, nullptr);
    k_final<<<TOK, 256>>>(norm_w, out);
}

// round 10
// speedup vs baseline: 1.1597x; 1.1597x over previous
#include <cuda_runtime.h>

#define TOK  4096
#define Dm   1024
#define Sdim 16
#define Edim 4
#define Hdim 2048
#define Ldim 2048
#define NCH  32      // scan chunks
#define CH   64      // chunk length (NCH*CH = Ldim)

// ---------------- scratch (device globals; no allocation) ----------------
__device__ float g_delta[(size_t)TOK * Dm];
__device__ float g_Bm[(size_t)TOK * Sdim];
__device__ float g_Cm[(size_t)TOK * Sdim];
__device__ float g_ssm[(size_t)TOK * Dm];
__device__ float g_hidden[(size_t)Edim * TOK * Hdim];    // 128 MB
__device__ float g_expout[(size_t)Edim * TOK * Dm];      // 64 MB
__device__ float g_hp[(size_t)2 * Dm * NCH * Sdim];
__device__ float g_ap[(size_t)2 * Dm * NCH * Sdim];
__device__ float g_hi[(size_t)2 * Dm * NCH * Sdim];
__device__ int   g_cnt[Edim];
__device__ int   g_idx[Edim * TOK];
__device__ int   g_tokexp[2 * TOK];
__device__ int   g_tokslot[2 * TOK];
__device__ float g_tokw[2 * TOK];

// ---------------- f32x2 helpers ----------------
static __device__ __forceinline__ unsigned long long dup2(float x) {
    unsigned long long r; unsigned u = __float_as_uint(x);
    asm("mov.b64 %0, {%1, %1};" : "=l"(r) : "r"(u));
    return r;
}
static __device__ __forceinline__ void ffma2(unsigned long long& c,
                                             unsigned long long a,
                                             unsigned long long b) {
    asm("fma.rn.f32x2 %0, %1, %2, %0;" : "+l"(c) : "l"(a), "l"(b));
}
union F4U { float4 f4; float f[4]; unsigned long long u2[2]; };

// ---------------- init ----------------
__global__ void k_init() {
    if (threadIdx.x < Edim) g_cnt[threadIdx.x] = 0;
}

// ---------------- generic 128x128x8 fp32 GEMM (R0-proven layout) ----------
// MODE 0: g_delta = softplus(x @ W_delta + b_delta)          (M=TOK,N=Dm,K=Dm)
// MODE 1: g_hidden[e] = silu(gather(ssm) @ Wg[e])            (M=cnt[e],N=Hdim,K=Dm)
// MODE 2: g_hidden[e] *= gather(ssm) @ Wu[e]                 (RMW)
// MODE 3: g_expout[e]  = g_hidden[e] @ Wd[e]                 (M=cnt[e],N=Dm,K=Hdim)
template <int MODE>
__global__ __launch_bounds__(256, 2)
void k_gemm(const float* __restrict__ Aext, const float* __restrict__ Bext,
            const float* __restrict__ bias) {
    constexpr int N = (MODE == 1 || MODE == 2) ? Hdim : Dm;
    constexpr int K = (MODE == 3) ? Hdim : Dm;
    const int e = blockIdx.z;

    const float* A; const float* B; int M;
    if (MODE == 0)      { A = Aext;                              B = Bext;                      M = TOK; }
    else if (MODE == 3) { A = g_hidden + (size_t)e * TOK * K;    B = Bext + (size_t)e * K * N;  M = g_cnt[e]; }
    else                { A = g_ssm;                             B = Bext + (size_t)e * K * N;  M = g_cnt[e]; }

    const int m0 = blockIdx.y * 128;
    const int n0 = blockIdx.x * 128;
    if (m0 >= M) return;

    __shared__ float As[8][128];
    __shared__ float Bs[8][128];

    const int tid  = threadIdx.x;
    const int arow = tid >> 1;
    const int acol = (tid & 1) * 4;
    const int brow = tid >> 5;
    const int bcol = (tid & 31) * 4;
    const int tx = tid & 15, ty = tid >> 4;

    bool avalid;
    const float* aptr;
    if (MODE == 1 || MODE == 2) {
        int mr = m0 + arow;
        avalid = mr < M;
        int gr = avalid ? g_idx[e * TOK + mr] : 0;
        aptr = A + (size_t)gr * K + acol;
    } else {
        avalid = (m0 + arow) < M;       // always true for MODE 0
        aptr = A + (size_t)(m0 + arow) * K + acol;
    }
    const float* bptr = B + (size_t)brow * N + n0 + bcol;

    float4 a_ld = avalid ? *(const float4*)aptr : make_float4(0.f, 0.f, 0.f, 0.f);
    float4 b_ld = *(const float4*)bptr;

    unsigned long long acc[8][4];
#pragma unroll
    for (int i = 0; i < 8; i++)
#pragma unroll
        for (int j = 0; j < 4; j++) acc[i][j] = 0ULL;

    const int KT = K / 8;
    for (int kt = 0; kt < KT; kt++) {
        As[acol + 0][arow] = a_ld.x;
        As[acol + 1][arow] = a_ld.y;
        As[acol + 2][arow] = a_ld.z;
        As[acol + 3][arow] = a_ld.w;
        *(float4*)&Bs[brow][bcol] = b_ld;
        __syncthreads();

        if (kt + 1 < KT) {
            a_ld = avalid ? *(const float4*)(aptr + (size_t)(kt + 1) * 8)
                          : make_float4(0.f, 0.f, 0.f, 0.f);
            b_ld = *(const float4*)(bptr + (size_t)(kt + 1) * 8 * N);
        }

#pragma unroll
        for (int k = 0; k < 8; k++) {
            F4U a0, a1, b0, b1;
            a0.f4 = *(const float4*)&As[k][ty * 4];
            a1.f4 = *(const float4*)&As[k][64 + ty * 4];
            b0.f4 = *(const float4*)&Bs[k][tx * 4];
            b1.f4 = *(const float4*)&Bs[k][64 + tx * 4];
            unsigned long long bb0 = b0.u2[0], bb1 = b0.u2[1];
            unsigned long long bb2 = b1.u2[0], bb3 = b1.u2[1];
#pragma unroll
            for (int i = 0; i < 8; i++) {
                float av = (i < 4) ? a0.f[i] : a1.f[i - 4];
                unsigned long long ad = dup2(av);
                ffma2(acc[i][0], ad, bb0);
                ffma2(acc[i][1], ad, bb1);
                ffma2(acc[i][2], ad, bb2);
                ffma2(acc[i][3], ad, bb3);
            }
        }
        __syncthreads();
    }

    // epilogue
#pragma unroll
    for (int i = 0; i < 8; i++) {
        int rloc = (i < 4) ? (ty * 4 + i) : (64 + ty * 4 + (i - 4));
        int r = m0 + rloc;
        if (MODE != 0 && r >= M) continue;
        F4U lo, hi;
        lo.u2[0] = acc[i][0]; lo.u2[1] = acc[i][1];
        hi.u2[0] = acc[i][2]; hi.u2[1] = acc[i][3];
        int c0 = n0 + tx * 4;
        int c1 = n0 + 64 + tx * 4;

        if (MODE == 0) {
            F4U o0, o1;
#pragma unroll
            for (int j = 0; j < 4; j++) {
                float v0 = lo.f[j] + bias[c0 + j];
                float v1 = hi.f[j] + bias[c1 + j];
                o0.f[j] = v0 > 20.f ? v0 : log1pf(__expf(v0));
                o1.f[j] = v1 > 20.f ? v1 : log1pf(__expf(v1));
            }
            *(float4*)&g_delta[(size_t)r * N + c0] = o0.f4;
            *(float4*)&g_delta[(size_t)r * N + c1] = o1.f4;
        } else if (MODE == 1) {
            float* O = g_hidden + (size_t)e * TOK * N;
            F4U o0, o1;
#pragma unroll
            for (int j = 0; j < 4; j++) {
                float v0 = lo.f[j], v1 = hi.f[j];
                o0.f[j] = v0 / (1.f + __expf(-v0));
                o1.f[j] = v1 / (1.f + __expf(-v1));
            }
            *(float4*)&O[(size_t)r * N + c0] = o0.f4;
            *(float4*)&O[(size_t)r * N + c1] = o1.f4;
        } else if (MODE == 2) {
            float* O = g_hidden + (size_t)e * TOK * N;
            F4U o0, o1;
            o0.f4 = *(const float4*)&O[(size_t)r * N + c0];
            o1.f4 = *(const float4*)&O[(size_t)r * N + c1];
#pragma unroll
            for (int j = 0; j < 4; j++) { o0.f[j] *= lo.f[j]; o1.f[j] *= hi.f[j]; }
            *(float4*)&O[(size_t)r * N + c0] = o0.f4;
            *(float4*)&O[(size_t)r * N + c1] = o1.f4;
        } else {
            float* O = g_expout + ((size_t)e * TOK + r) * N;
            *(float4*)&O[c0] = lo.f4;
            *(float4*)&O[c1] = hi.f4;
        }
    }
}

// ---------------- Bm / Cm ----------------
__global__ void k_bc(const float* __restrict__ x, const float* __restrict__ WB,
                     const float* __restrict__ WC) {
    __shared__ float xs[Dm];
    __shared__ float red[8][32];
    int n = blockIdx.x, tid = threadIdx.x;
    const float* xr = x + (size_t)n * Dm;
    for (int i = tid; i < Dm; i += 256) xs[i] = xr[i];
    __syncthreads();
    int o = tid & 31, part = tid >> 5;
    const float* W = (o < 16) ? WB : WC;
    int s = o & 15;
    float acc = 0.f;
    int k0 = part * 128;
#pragma unroll 8
    for (int k = 0; k < 128; k++) acc = fmaf(xs[k0 + k], W[(k0 + k) * Sdim + s], acc);
    red[part][o] = acc;
    __syncthreads();
    if (tid < 32) {
        float a = 0.f;
#pragma unroll
        for (int p = 0; p < 8; p++) a += red[p][tid];
        if (tid < 16) g_Bm[n * Sdim + tid] = a;
        else          g_Cm[n * Sdim + (tid - 16)] = a;
    }
}

// ============== chunked scan (R1, ncu-verified) ==============
__global__ __launch_bounds__(256)
void k_scanA(const float* __restrict__ x, const float* __restrict__ A_log) {
    const int d = blockIdx.x * 256 + threadIdx.x;
    const int c = blockIdx.y;
    const int b = blockIdx.z;
    __shared__ float sB[CH * Sdim];
    const float* bb = g_Bm + ((size_t)b * Ldim + c * CH) * Sdim;
    for (int i = threadIdx.x; i < CH * Sdim; i += 256) sB[i] = bb[i];
    __syncthreads();
    float Av[16];
#pragma unroll
    for (int q = 0; q < 4; q++) {
        float4 al = *(const float4*)&A_log[d * Sdim + q * 4];
        Av[q*4+0] = -__expf(al.x); Av[q*4+1] = -__expf(al.y);
        Av[q*4+2] = -__expf(al.z); Av[q*4+3] = -__expf(al.w);
    }
    float h[16], ap[16];
#pragma unroll
    for (int s = 0; s < 16; s++) { h[s] = 0.f; ap[s] = 1.f; }
    const size_t base = ((size_t)b * Ldim + c * CH) * Dm + d;
    for (int t = 0; t < CH; t++) {
        float xt = x[base + (size_t)t * Dm];
        float dt = g_delta[base + (size_t)t * Dm];
        float4 B0 = *(const float4*)&sB[t * 16 + 0];
        float4 B1 = *(const float4*)&sB[t * 16 + 4];
        float4 B2 = *(const float4*)&sB[t * 16 + 8];
        float4 B3 = *(const float4*)&sB[t * 16 + 12];
        float Bv[16] = {B0.x,B0.y,B0.z,B0.w, B1.x,B1.y,B1.z,B1.w,
                        B2.x,B2.y,B2.z,B2.w, B3.x,B3.y,B3.z,B3.w};
#pragma unroll
        for (int s = 0; s < 16; s++) {
            float a = __expf(fminf(dt * Av[s], 10.f));
            float u = fminf(fmaxf(dt * Bv[s], -10.f), 10.f) * xt;
            h[s] = fmaf(a, h[s], u);
            ap[s] *= a;
        }
    }
    const size_t oi = (((size_t)b * Dm + d) * NCH + c) * Sdim;
#pragma unroll
    for (int q = 0; q < 4; q++) {
        *(float4*)&g_hp[oi + q * 4] = make_float4(h[q*4], h[q*4+1], h[q*4+2], h[q*4+3]);
        *(float4*)&g_ap[oi + q * 4] = make_float4(ap[q*4], ap[q*4+1], ap[q*4+2], ap[q*4+3]);
    }
}

__global__ void k_scanB() {
    int g = blockIdx.x * 256 + threadIdx.x;
    size_t base = (size_t)(g >> 4) * NCH * Sdim + (g & 15);
    float hi = 0.f;
    for (int c = 0; c < NCH; c++) {
        g_hi[base + (size_t)c * Sdim] = hi;
        hi = fmaf(g_ap[base + (size_t)c * Sdim], hi, g_hp[base + (size_t)c * Sdim]);
    }
}

__global__ __launch_bounds__(256)
void k_scanC(const float* __restrict__ x, const float* __restrict__ A_log,
             const float* __restrict__ Dp) {
    const int d = blockIdx.x * 256 + threadIdx.x;
    const int c = blockIdx.y;
    const int b = blockIdx.z;
    __shared__ float sB[CH * Sdim];
    __shared__ float sC[CH * Sdim];
    {
        const float* bb = g_Bm + ((size_t)b * Ldim + c * CH) * Sdim;
        const float* cc = g_Cm + ((size_t)b * Ldim + c * CH) * Sdim;
        for (int i = threadIdx.x; i < CH * Sdim; i += 256) { sB[i] = bb[i]; sC[i] = cc[i]; }
    }
    __syncthreads();
    float Av[16];
#pragma unroll
    for (int q = 0; q < 4; q++) {
        float4 al = *(const float4*)&A_log[d * Sdim + q * 4];
        Av[q*4+0] = -__expf(al.x); Av[q*4+1] = -__expf(al.y);
        Av[q*4+2] = -__expf(al.z); Av[q*4+3] = -__expf(al.w);
    }
    const float dpar = Dp[d];
    float h[16];
    const size_t hidx = (((size_t)b * Dm + d) * NCH + c) * Sdim;
#pragma unroll
    for (int q = 0; q < 4; q++) {
        float4 hv = *(const float4*)&g_hi[hidx + q * 4];
        h[q*4] = hv.x; h[q*4+1] = hv.y; h[q*4+2] = hv.z; h[q*4+3] = hv.w;
    }
    const size_t base = ((size_t)b * Ldim + c * CH) * Dm + d;
    for (int t = 0; t < CH; t++) {
        float xt = x[base + (size_t)t * Dm];
        float dt = g_delta[base + (size_t)t * Dm];
        float4 B0 = *(const float4*)&sB[t * 16 + 0];
        float4 B1 = *(const float4*)&sB[t * 16 + 4];
        float4 B2 = *(const float4*)&sB[t * 16 + 8];
        float4 B3 = *(const float4*)&sB[t * 16 + 12];
        float4 C0 = *(const float4*)&sC[t * 16 + 0];
        float4 C1 = *(const float4*)&sC[t * 16 + 4];
        float4 C2 = *(const float4*)&sC[t * 16 + 8];
        float4 C3 = *(const float4*)&sC[t * 16 + 12];
        float Bv[16] = {B0.x,B0.y,B0.z,B0.w, B1.x,B1.y,B1.z,B1.w,
                        B2.x,B2.y,B2.z,B2.w, B3.x,B3.y,B3.z,B3.w};
        float Cv[16] = {C0.x,C0.y,C0.z,C0.w, C1.x,C1.y,C1.z,C1.w,
                        C2.x,C2.y,C2.z,C2.w, C3.x,C3.y,C3.z,C3.w};
        float y = xt * dpar;
#pragma unroll
        for (int s = 0; s < 16; s++) {
            float a = __expf(fminf(dt * Av[s], 10.f));
            float u = fminf(fmaxf(dt * Bv[s], -10.f), 10.f) * xt;
            float hv = fmaf(a, h[s], u);
            hv = fminf(fmaxf(hv, -10000.f), 10000.f);
            h[s] = hv;
            y = fmaf(hv, Cv[s], y);
        }
        g_ssm[base + (size_t)t * Dm] = y;
    }
}

// ---------------- router ----------------
__global__ void k_router(const float* __restrict__ Wr) {
    int gw = (blockIdx.x * blockDim.x + threadIdx.x) >> 5;
    int lane = threadIdx.x & 31;
    const float* xr = g_ssm + (size_t)gw * Dm;
    float a0 = 0, a1 = 0, a2 = 0, a3 = 0;
    for (int k = lane; k < Dm; k += 32) {
        float xv = xr[k];
        float4 w = *(const float4*)&Wr[k * 4];
        a0 = fmaf(xv, w.x, a0); a1 = fmaf(xv, w.y, a1);
        a2 = fmaf(xv, w.z, a2); a3 = fmaf(xv, w.w, a3);
    }
#pragma unroll
    for (int m = 16; m > 0; m >>= 1) {
        a0 += __shfl_xor_sync(~0u, a0, m);
        a1 += __shfl_xor_sync(~0u, a1, m);
        a2 += __shfl_xor_sync(~0u, a2, m);
        a3 += __shfl_xor_sync(~0u, a3, m);
    }
    if (lane == 0) {
        float l[4] = {a0, a1, a2, a3};
        float mx = fmaxf(fmaxf(l[0], l[1]), fmaxf(l[2], l[3]));
        float p[4]; float Z = 0.f;
#pragma unroll
        for (int q = 0; q < 4; q++) { p[q] = __expf(l[q] - mx); Z += p[q]; }
        float inv = 1.f / Z;
#pragma unroll
        for (int q = 0; q < 4; q++) p[q] *= inv;
        int i0 = 0;
#pragma unroll
        for (int q = 1; q < 4; q++) if (p[q] > p[i0]) i0 = q;
        int i1 = -1;
#pragma unroll
        for (int q = 0; q < 4; q++) if (q != i0 && (i1 < 0 || p[q] > p[i1])) i1 = q;
        float w0 = p[i0], w1 = p[i1];
        float den = w0 + w1 + 1e-9f;
        w0 /= den; w1 /= den;
        int pos0 = atomicAdd(&g_cnt[i0], 1);
        g_idx[i0 * TOK + pos0] = gw;
        int pos1 = atomicAdd(&g_cnt[i1], 1);
        g_idx[i1 * TOK + pos1] = gw;
        g_tokexp[2 * gw]     = i0; g_tokslot[2 * gw]     = pos0; g_tokw[2 * gw]     = w0;
        g_tokexp[2 * gw + 1] = i1; g_tokslot[2 * gw + 1] = pos1; g_tokw[2 * gw + 1] = w1;
    }
}

// ---------------- rmsnorm over hidden rows ----------------
__global__ void k_rmsg(const float* __restrict__ wn) {
    int e = blockIdx.y, i = blockIdx.x;
    if (i >= g_cnt[e]) return;
    float* row = g_hidden + ((size_t)e * TOK + i) * Hdim;
    __shared__ float red[8];
    int tid = threadIdx.x, lane = tid & 31, w = tid >> 5;
    float v[8];
    float ss = 0.f;
#pragma unroll
    for (int q = 0; q < 8; q++) { v[q] = row[tid + q * 256]; ss += v[q] * v[q]; }
#pragma unroll
    for (int m = 16; m > 0; m >>= 1) ss += __shfl_xor_sync(~0u, ss, m);
    if (lane == 0) red[w] = ss;
    __syncthreads();
    if (tid == 0) {
        float t = 0.f;
#pragma unroll
        for (int j = 0; j < 8; j++) t += red[j];
        red[0] = rsqrtf(t * (1.f / Hdim) + 1e-6f);
    }
    __syncthreads();
    float r = red[0];
#pragma unroll
    for (int q = 0; q < 8; q++) row[tid + q * 256] = wn[e * Hdim + tid + q * 256] * v[q] * r;
}

// ---------------- final: out = rmsnorm(ssm + w0*eo0 + w1*eo1, norm_w) -------
__global__ void k_final(const float* __restrict__ nw, float* __restrict__ out) {
    int n = blockIdx.x;
    int tid = threadIdx.x, lane = tid & 31, w = tid >> 5;
    __shared__ float red[8];
    const float* s = g_ssm + (size_t)n * Dm;
    int e0 = g_tokexp[2 * n], e1 = g_tokexp[2 * n + 1];
    int s0 = g_tokslot[2 * n], s1 = g_tokslot[2 * n + 1];
    float w0 = g_tokw[2 * n], w1 = g_tokw[2 * n + 1];
    const float* r0 = g_expout + ((size_t)e0 * TOK + s0) * Dm;
    const float* r1 = g_expout + ((size_t)e1 * TOK + s1) * Dm;
    float v[4];
    float ss = 0.f;
#pragma unroll
    for (int q = 0; q < 4; q++) {
        int i = tid + q * 256;
        float t = s[i] + w0 * r0[i] + w1 * r1[i];
        v[q] = t; ss += t * t;
    }
#pragma unroll
    for (int mm = 16; mm > 0; mm >>= 1) ss += __shfl_xor_sync(~0u, ss, mm);
    if (lane == 0) red[w] = ss;
    __syncthreads();
    if (tid == 0) {
        float t = 0.f;
#pragma unroll
        for (int j = 0; j < 8; j++) t += red[j];
        red[0] = rsqrtf(t * (1.f / Dm) + 1e-6f);
    }
    __syncthreads();
    float r = red[0];
#pragma unroll
    for (int q = 0; q < 4; q++)
        out[(size_t)n * Dm + tid + q * 256] = nw[tid + q * 256] * v[q] * r;
}

// ---------------- launch ----------------
extern "C" void kernel_launch(void* const* d_in, const int* in_sizes, int n_in,
                              void* d_out, int out_size) {
    const float* x        = (const float*)d_in[0];
    const float* A_log    = (const float*)d_in[1];
    const float* D_param  = (const float*)d_in[2];
    const float* W_delta  = (const float*)d_in[3];
    const float* b_delta  = (const float*)d_in[4];
    const float* W_B      = (const float*)d_in[5];
    const float* W_C      = (const float*)d_in[6];
    const float* W_router = (const float*)d_in[7];
    const float* Wg       = (const float*)d_in[8];
    const float* Wu       = (const float*)d_in[9];
    const float* Wd       = (const float*)d_in[10];
    const float* wn_exp   = (const float*)d_in[11];
    const float* norm_w   = (const float*)d_in[12];
    float* out = (float*)d_out;

    k_init<<<1, 32>>>();
    k_gemm<0><<<dim3(Dm / 128, TOK / 128, 1), 256>>>(x, W_delta, b_delta);
    k_bc<<<TOK, 256>>>(x, W_B, W_C);
    k_scanA<<<dim3(Dm / 256, NCH, 2), 256>>>(x, A_log);
    k_scanB<<<(2 * Dm * Sdim) / 256, 256>>>();
    k_scanC<<<dim3(Dm / 256, NCH, 2), 256>>>(x, A_log, D_param);
    k_router<<<TOK / 8, 256>>>(W_router);
    k_gemm<1><<<dim3(Hdim / 128, TOK / 128, Edim), 256>>>(nullptr, Wg, nullptr);
    k_gemm<2><<<dim3(Hdim / 128, TOK / 128, Edim), 256>>>(nullptr, Wu, nullptr);
    k_rmsg<<<dim3(TOK, Edim), 256>>>(wn_exp);
    k_gemm<3><<<dim3(Dm / 128, TOK / 128, Edim), 256>>>(nullptr, Wd, nullptr);
    k_final<<<TOK, 256>>>(norm_w, out);
}

// round 13
// speedup vs baseline: 1.4726x; 1.2698x over previous
#include <cuda_runtime.h>
#include <cuda_bf16.h>
#include <cstdint>

#define TOK  4096
#define Dm   1024
#define Sdim 16
#define Edim 4
#define Hdim 2048
#define Ldim 2048
#define NCH  32
#define CH   64
#define SP   136   // padded smem row stride (u32)

// ---------------- scratch (device globals; no allocation) ----------------
__device__ float g_delta[(size_t)TOK * Dm];
__device__ float g_Bm[(size_t)TOK * Sdim];
__device__ float g_Cm[(size_t)TOK * Sdim];
__device__ float g_ssm[(size_t)TOK * Dm];
__device__ float g_hidden[(size_t)Edim * TOK * Hdim];    // 128 MB
__device__ float g_expout[(size_t)Edim * TOK * Dm];      // 64 MB
__device__ float g_hp[(size_t)2 * Dm * NCH * Sdim];
__device__ float g_ap[(size_t)2 * Dm * NCH * Sdim];
__device__ float g_hi[(size_t)2 * Dm * NCH * Sdim];
__device__ int   g_cnt[Edim];
__device__ int   g_idx[Edim * TOK];
__device__ int   g_tokexp[2 * TOK];
__device__ int   g_tokslot[2 * TOK];
__device__ float g_tokw[2 * TOK];
// packed split-bf16 weights, stage layout: [(e*(N/128)+nt)*(K/32)+kt][16][128] u32
__device__ uint32_t g_WgP_h[(size_t)Edim * Hdim * Dm / 2];   // 16 MB each
__device__ uint32_t g_WgP_l[(size_t)Edim * Hdim * Dm / 2];
__device__ uint32_t g_WuP_h[(size_t)Edim * Hdim * Dm / 2];
__device__ uint32_t g_WuP_l[(size_t)Edim * Hdim * Dm / 2];
__device__ uint32_t g_WdP_h[(size_t)Edim * Dm * Hdim / 2];
__device__ uint32_t g_WdP_l[(size_t)Edim * Dm * Hdim / 2];

// ---------------- helpers ----------------
static __device__ __forceinline__ unsigned long long dup2(float x) {
    unsigned long long r; unsigned u = __float_as_uint(x);
    asm("mov.b64 %0, {%1, %1};" : "=l"(r) : "r"(u));
    return r;
}
static __device__ __forceinline__ void ffma2(unsigned long long& c,
                                             unsigned long long a,
                                             unsigned long long b) {
    asm("fma.rn.f32x2 %0, %1, %2, %0;" : "+l"(c) : "l"(a), "l"(b));
}
union F4U { float4 f4; float f[4]; unsigned long long u2[2]; };

static __device__ __forceinline__ void mma16816(float* c,
        uint32_t a0, uint32_t a1, uint32_t a2, uint32_t a3,
        uint32_t b0, uint32_t b1) {
    asm volatile("mma.sync.aligned.m16n8k16.row.col.f32.bf16.bf16.f32 "
        "{%0,%1,%2,%3}, {%4,%5,%6,%7}, {%8,%9}, {%0,%1,%2,%3};"
        : "+f"(c[0]), "+f"(c[1]), "+f"(c[2]), "+f"(c[3])
        : "r"(a0), "r"(a1), "r"(a2), "r"(a3), "r"(b0), "r"(b1));
}
static __device__ __forceinline__ uint32_t pack_hi(float x, float y, uint32_t& lo) {
    __nv_bfloat162 h = __floats2bfloat162_rn(x, y);
    float r0 = x - __bfloat162float(h.x);
    float r1 = y - __bfloat162float(h.y);
    __nv_bfloat162 l = __floats2bfloat162_rn(r0, r1);
    lo = *(uint32_t*)&l;
    return *(uint32_t*)&h;
}

// ---------------- init ----------------
__global__ void k_init() {
    if (threadIdx.x < Edim) g_cnt[threadIdx.x] = 0;
}

// ---------------- weight prep: [K][N] fp32 -> packed stage layout ----------
__global__ __launch_bounds__(256)
void k_prep(const float* __restrict__ W, uint32_t* __restrict__ oh,
            uint32_t* __restrict__ ol, int K, int N) {
    const int e = blockIdx.z;
    const int n0 = blockIdx.x * 128, k0 = blockIdx.y * 32;
    const int nn = threadIdx.x & 127, half = threadIdx.x >> 7;
    const float* Wb = W + (size_t)e * K * N;
    const size_t base = ((size_t)(e * (N / 128) + blockIdx.x) * (K / 32) + blockIdx.y) * 2048;
#pragma unroll
    for (int j = 0; j < 8; j++) {
        int pr = half * 8 + j;
        float v0 = Wb[(size_t)(k0 + 2 * pr) * N + n0 + nn];
        float v1 = Wb[(size_t)(k0 + 2 * pr + 1) * N + n0 + nn];
        uint32_t lo, hi = pack_hi(v0, v1, lo);
        oh[base + pr * 128 + nn] = hi;
        ol[base + pr * 128 + nn] = lo;
    }
}

// ---------------- delta GEMM (FFMA2, R0-proven) ----------------
__global__ __launch_bounds__(256, 2)
void k_gemm0(const float* __restrict__ A, const float* __restrict__ B,
             const float* __restrict__ bias) {
    constexpr int N = Dm, K = Dm;
    const int m0 = blockIdx.y * 128;
    const int n0 = blockIdx.x * 128;
    __shared__ float As[8][128];
    __shared__ float Bs[8][128];
    const int tid = threadIdx.x;
    const int arow = tid >> 1, acol = (tid & 1) * 4;
    const int brow = tid >> 5, bcol = (tid & 31) * 4;
    const int tx = tid & 15, ty = tid >> 4;
    const float* aptr = A + (size_t)(m0 + arow) * K + acol;
    const float* bptr = B + (size_t)brow * N + n0 + bcol;
    float4 a_ld = *(const float4*)aptr;
    float4 b_ld = *(const float4*)bptr;
    unsigned long long acc[8][4];
#pragma unroll
    for (int i = 0; i < 8; i++)
#pragma unroll
        for (int j = 0; j < 4; j++) acc[i][j] = 0ULL;
    const int KT = K / 8;
    for (int kt = 0; kt < KT; kt++) {
        As[acol + 0][arow] = a_ld.x; As[acol + 1][arow] = a_ld.y;
        As[acol + 2][arow] = a_ld.z; As[acol + 3][arow] = a_ld.w;
        *(float4*)&Bs[brow][bcol] = b_ld;
        __syncthreads();
        if (kt + 1 < KT) {
            a_ld = *(const float4*)(aptr + (size_t)(kt + 1) * 8);
            b_ld = *(const float4*)(bptr + (size_t)(kt + 1) * 8 * N);
        }
#pragma unroll
        for (int k = 0; k < 8; k++) {
            F4U a0, a1, b0, b1;
            a0.f4 = *(const float4*)&As[k][ty * 4];
            a1.f4 = *(const float4*)&As[k][64 + ty * 4];
            b0.f4 = *(const float4*)&Bs[k][tx * 4];
            b1.f4 = *(const float4*)&Bs[k][64 + tx * 4];
            unsigned long long bb0 = b0.u2[0], bb1 = b0.u2[1];
            unsigned long long bb2 = b1.u2[0], bb3 = b1.u2[1];
#pragma unroll
            for (int i = 0; i < 8; i++) {
                float av = (i < 4) ? a0.f[i] : a1.f[i - 4];
                unsigned long long ad = dup2(av);
                ffma2(acc[i][0], ad, bb0);
                ffma2(acc[i][1], ad, bb1);
                ffma2(acc[i][2], ad, bb2);
                ffma2(acc[i][3], ad, bb3);
            }
        }
        __syncthreads();
    }
#pragma unroll
    for (int i = 0; i < 8; i++) {
        int rloc = (i < 4) ? (ty * 4 + i) : (64 + ty * 4 + (i - 4));
        int r = m0 + rloc;
        F4U lo, hi;
        lo.u2[0] = acc[i][0]; lo.u2[1] = acc[i][1];
        hi.u2[0] = acc[i][2]; hi.u2[1] = acc[i][3];
        int c0 = n0 + tx * 4, c1 = n0 + 64 + tx * 4;
        F4U o0, o1;
#pragma unroll
        for (int j = 0; j < 4; j++) {
            float v0 = lo.f[j] + bias[c0 + j];
            float v1 = hi.f[j] + bias[c1 + j];
            o0.f[j] = v0 > 20.f ? v0 : log1pf(__expf(v0));
            o1.f[j] = v1 > 20.f ? v1 : log1pf(__expf(v1));
        }
        *(float4*)&g_delta[(size_t)r * N + c0] = o0.f4;
        *(float4*)&g_delta[(size_t)r * N + c1] = o1.f4;
    }
}

// ============ MoE GEMMs via mma.sync bf16 split-precision ============
struct StageRegs { uint32_t ah[8], al[8]; uint4 bh[2], bl[2]; };

template <int MODE>
static __device__ __forceinline__ void load_stage(StageRegs& s,
        const float* arow, bool aval,
        const uint32_t* wh, const uint32_t* wl, int tid, int kh, int kt) {
    const float* p = arow + kt * 32 + kh * 16;
#pragma unroll
    for (int j = 0; j < 4; j++) {
        float4 f = aval ? *(const float4*)(p + j * 4) : make_float4(0.f, 0.f, 0.f, 0.f);
        s.ah[j * 2 + 0] = pack_hi(f.x, f.y, s.al[j * 2 + 0]);
        s.ah[j * 2 + 1] = pack_hi(f.z, f.w, s.al[j * 2 + 1]);
    }
    const uint32_t* whk = wh + (size_t)kt * 2048;
    const uint32_t* wlk = wl + (size_t)kt * 2048;
#pragma unroll
    for (int j = 0; j < 2; j++) {
        s.bh[j] = *(const uint4*)(whk + (tid + j * 256) * 4);
        s.bl[j] = *(const uint4*)(wlk + (tid + j * 256) * 4);
    }
}

template <int MODE>
__global__ __launch_bounds__(256)
void k_moe(const uint32_t* __restrict__ Wh, const uint32_t* __restrict__ Wl) {
    constexpr int N = (MODE == 3) ? Dm : Hdim;
    constexpr int K = (MODE == 3) ? Hdim : Dm;
    const int e = blockIdx.z;
    const int M = g_cnt[e];
    const int m0 = blockIdx.y * 128, n0 = blockIdx.x * 128;
    if (m0 >= M) return;

    __shared__ uint32_t Ah[16][SP], Al[16][SP], Bh[16][SP], Bl[16][SP];
    __shared__ int rowid[128];

    const int tid = threadIdx.x;
    if (MODE != 3 && tid < 128)
        rowid[tid] = (m0 + tid < M) ? g_idx[e * TOK + m0 + tid] : -1;
    __syncthreads();

    const int am = tid & 127, kh = tid >> 7;
    const float* arow; bool aval;
    if (MODE == 3) {
        aval = (m0 + am) < M;
        arow = g_hidden + ((size_t)e * TOK + m0 + am) * K;
    } else {
        int rid = rowid[am];
        aval = rid >= 0;
        arow = g_ssm + (size_t)(aval ? rid : 0) * K;
    }
    const uint32_t* whb = Wh + ((size_t)(e * (N / 128) + blockIdx.x) * (K / 32)) * 2048;
    const uint32_t* wlb = Wl + ((size_t)(e * (N / 128) + blockIdx.x) * (K / 32)) * 2048;

    const int wid = tid >> 5, lane = tid & 31;
    const int g = lane >> 2, t = lane & 3;
    const int wm = (wid & 1) * 64, wn = (wid >> 1) * 32;

    float acc[4][4][4];
#pragma unroll
    for (int a = 0; a < 4; a++)
#pragma unroll
        for (int b = 0; b < 4; b++)
#pragma unroll
            for (int cc = 0; cc < 4; cc++) acc[a][b][cc] = 0.f;

    StageRegs sr;
    load_stage<MODE>(sr, arow, aval, whb, wlb, tid, kh, 0);

    const int KT = K / 32;
    for (int kt = 0; kt < KT; kt++) {
        __syncthreads();
#pragma unroll
        for (int j = 0; j < 8; j++) { Ah[kh * 8 + j][am] = sr.ah[j]; Al[kh * 8 + j][am] = sr.al[j]; }
#pragma unroll
        for (int j = 0; j < 2; j++) {
            int f = tid + j * 256; int row = f >> 5, c4 = (f & 31) * 4;
            *(uint4*)&Bh[row][c4] = sr.bh[j];
            *(uint4*)&Bl[row][c4] = sr.bl[j];
        }
        __syncthreads();
        if (kt + 1 < KT) load_stage<MODE>(sr, arow, aval, whb, wlb, tid, kh, kt + 1);

#pragma unroll
        for (int kk = 0; kk < 2; kk++) {
            const int ko = kk * 8;
            uint32_t fah[4][4], fal[4][4];
#pragma unroll
            for (int mt = 0; mt < 4; mt++) {
                int mb = wm + mt * 16 + g;
                fah[mt][0] = Ah[ko + t][mb];     fah[mt][1] = Ah[ko + t][mb + 8];
                fah[mt][2] = Ah[ko + t + 4][mb]; fah[mt][3] = Ah[ko + t + 4][mb + 8];
                fal[mt][0] = Al[ko + t][mb];     fal[mt][1] = Al[ko + t][mb + 8];
                fal[mt][2] = Al[ko + t + 4][mb]; fal[mt][3] = Al[ko + t + 4][mb + 8];
            }
#pragma unroll
            for (int nt = 0; nt < 4; nt++) {
                int nb = wn + nt * 8 + g;
                uint32_t bh0 = Bh[ko + t][nb], bh1 = Bh[ko + t + 4][nb];
                uint32_t bl0 = Bl[ko + t][nb], bl1 = Bl[ko + t + 4][nb];
#pragma unroll
                for (int mt = 0; mt < 4; mt++) {
                    mma16816(acc[mt][nt], fah[mt][0], fah[mt][1], fah[mt][2], fah[mt][3], bh0, bh1);
                    mma16816(acc[mt][nt], fah[mt][0], fah[mt][1], fah[mt][2], fah[mt][3], bl0, bl1);
                    mma16816(acc[mt][nt], fal[mt][0], fal[mt][1], fal[mt][2], fal[mt][3], bh0, bh1);
                }
            }
        }
    }

    // epilogue
#pragma unroll
    for (int mt = 0; mt < 4; mt++) {
#pragma unroll
        for (int nt = 0; nt < 4; nt++) {
            int r0 = m0 + wm + mt * 16 + g;
            int r1 = r0 + 8;
            int c = n0 + wn + nt * 8 + t * 2;
            float* C = acc[mt][nt];
            if (MODE == 1) {
                float* O = g_hidden + (size_t)e * TOK * N;
                if (r0 < M) {
                    float2 o = { C[0] / (1.f + __expf(-C[0])), C[1] / (1.f + __expf(-C[1])) };
                    *(float2*)&O[(size_t)r0 * N + c] = o;
                }
                if (r1 < M) {
                    float2 o = { C[2] / (1.f + __expf(-C[2])), C[3] / (1.f + __expf(-C[3])) };
                    *(float2*)&O[(size_t)r1 * N + c] = o;
                }
            } else if (MODE == 2) {
                float* O = g_hidden + (size_t)e * TOK * N;
                if (r0 < M) {
                    float2 o = *(float2*)&O[(size_t)r0 * N + c];
                    o.x *= C[0]; o.y *= C[1];
                    *(float2*)&O[(size_t)r0 * N + c] = o;
                }
                if (r1 < M) {
                    float2 o = *(float2*)&O[(size_t)r1 * N + c];
                    o.x *= C[2]; o.y *= C[3];
                    *(float2*)&O[(size_t)r1 * N + c] = o;
                }
            } else {
                float* O = g_expout + (size_t)e * TOK * N;
                if (r0 < M) { float2 o = { C[0], C[1] }; *(float2*)&O[(size_t)r0 * N + c] = o; }
                if (r1 < M) { float2 o = { C[2], C[3] }; *(float2*)&O[(size_t)r1 * N + c] = o; }
            }
        }
    }
}

// ---------------- Bm / Cm ----------------
__global__ void k_bc(const float* __restrict__ x, const float* __restrict__ WB,
                     const float* __restrict__ WC) {
    __shared__ float xs[Dm];
    __shared__ float red[8][32];
    int n = blockIdx.x, tid = threadIdx.x;
    const float* xr = x + (size_t)n * Dm;
    for (int i = tid; i < Dm; i += 256) xs[i] = xr[i];
    __syncthreads();
    int o = tid & 31, part = tid >> 5;
    const float* W = (o < 16) ? WB : WC;
    int s = o & 15;
    float acc = 0.f;
    int k0 = part * 128;
#pragma unroll 8
    for (int k = 0; k < 128; k++) acc = fmaf(xs[k0 + k], W[(k0 + k) * Sdim + s], acc);
    red[part][o] = acc;
    __syncthreads();
    if (tid < 32) {
        float a = 0.f;
#pragma unroll
        for (int p = 0; p < 8; p++) a += red[p][tid];
        if (tid < 16) g_Bm[n * Sdim + tid] = a;
        else          g_Cm[n * Sdim + (tid - 16)] = a;
    }
}

// ============== chunked scan (measured-good) ==============
__global__ __launch_bounds__(256)
void k_scanA(const float* __restrict__ x, const float* __restrict__ A_log) {
    const int d = blockIdx.x * 256 + threadIdx.x;
    const int c = blockIdx.y;
    const int b = blockIdx.z;
    __shared__ float sB[CH * Sdim];
    const float* bb = g_Bm + ((size_t)b * Ldim + c * CH) * Sdim;
    for (int i = threadIdx.x; i < CH * Sdim; i += 256) sB[i] = bb[i];
    __syncthreads();
    float Av[16];
#pragma unroll
    for (int q = 0; q < 4; q++) {
        float4 al = *(const float4*)&A_log[d * Sdim + q * 4];
        Av[q*4+0] = -__expf(al.x); Av[q*4+1] = -__expf(al.y);
        Av[q*4+2] = -__expf(al.z); Av[q*4+3] = -__expf(al.w);
    }
    float h[16], ap[16];
#pragma unroll
    for (int s = 0; s < 16; s++) { h[s] = 0.f; ap[s] = 1.f; }
    const size_t base = ((size_t)b * Ldim + c * CH) * Dm + d;
    for (int t = 0; t < CH; t++) {
        float xt = x[base + (size_t)t * Dm];
        float dt = g_delta[base + (size_t)t * Dm];
        float4 B0 = *(const float4*)&sB[t * 16 + 0];
        float4 B1 = *(const float4*)&sB[t * 16 + 4];
        float4 B2 = *(const float4*)&sB[t * 16 + 8];
        float4 B3 = *(const float4*)&sB[t * 16 + 12];
        float Bv[16] = {B0.x,B0.y,B0.z,B0.w, B1.x,B1.y,B1.z,B1.w,
                        B2.x,B2.y,B2.z,B2.w, B3.x,B3.y,B3.z,B3.w};
#pragma unroll
        for (int s = 0; s < 16; s++) {
            float a = __expf(fminf(dt * Av[s], 10.f));
            float u = fminf(fmaxf(dt * Bv[s], -10.f), 10.f) * xt;
            h[s] = fmaf(a, h[s], u);
            ap[s] *= a;
        }
    }
    const size_t oi = (((size_t)b * Dm + d) * NCH + c) * Sdim;
#pragma unroll
    for (int q = 0; q < 4; q++) {
        *(float4*)&g_hp[oi + q * 4] = make_float4(h[q*4], h[q*4+1], h[q*4+2], h[q*4+3]);
        *(float4*)&g_ap[oi + q * 4] = make_float4(ap[q*4], ap[q*4+1], ap[q*4+2], ap[q*4+3]);
    }
}

__global__ void k_scanB() {
    int g = blockIdx.x * 256 + threadIdx.x;
    size_t base = (size_t)(g >> 4) * NCH * Sdim + (g & 15);
    float hi = 0.f;
    for (int c = 0; c < NCH; c++) {
        g_hi[base + (size_t)c * Sdim] = hi;
        hi = fmaf(g_ap[base + (size_t)c * Sdim], hi, g_hp[base + (size_t)c * Sdim]);
    }
}

__global__ __launch_bounds__(256)
void k_scanC(const float* __restrict__ x, const float* __restrict__ A_log,
             const float* __restrict__ Dp) {
    const int d = blockIdx.x * 256 + threadIdx.x;
    const int c = blockIdx.y;
    const int b = blockIdx.z;
    __shared__ float sB[CH * Sdim];
    __shared__ float sC[CH * Sdim];
    {
        const float* bb = g_Bm + ((size_t)b * Ldim + c * CH) * Sdim;
        const float* cc = g_Cm + ((size_t)b * Ldim + c * CH) * Sdim;
        for (int i = threadIdx.x; i < CH * Sdim; i += 256) { sB[i] = bb[i]; sC[i] = cc[i]; }
    }
    __syncthreads();
    float Av[16];
#pragma unroll
    for (int q = 0; q < 4; q++) {
        float4 al = *(const float4*)&A_log[d * Sdim + q * 4];
        Av[q*4+0] = -__expf(al.x); Av[q*4+1] = -__expf(al.y);
        Av[q*4+2] = -__expf(al.z); Av[q*4+3] = -__expf(al.w);
    }
    const float dpar = Dp[d];
    float h[16];
    const size_t hidx = (((size_t)b * Dm + d) * NCH + c) * Sdim;
#pragma unroll
    for (int q = 0; q < 4; q++) {
        float4 hv = *(const float4*)&g_hi[hidx + q * 4];
        h[q*4] = hv.x; h[q*4+1] = hv.y; h[q*4+2] = hv.z; h[q*4+3] = hv.w;
    }
    const size_t base = ((size_t)b * Ldim + c * CH) * Dm + d;
    for (int t = 0; t < CH; t++) {
        float xt = x[base + (size_t)t * Dm];
        float dt = g_delta[base + (size_t)t * Dm];
        float4 B0 = *(const float4*)&sB[t * 16 + 0];
        float4 B1 = *(const float4*)&sB[t * 16 + 4];
        float4 B2 = *(const float4*)&sB[t * 16 + 8];
        float4 B3 = *(const float4*)&sB[t * 16 + 12];
        float4 C0 = *(const float4*)&sC[t * 16 + 0];
        float4 C1 = *(const float4*)&sC[t * 16 + 4];
        float4 C2 = *(const float4*)&sC[t * 16 + 8];
        float4 C3 = *(const float4*)&sC[t * 16 + 12];
        float Bv[16] = {B0.x,B0.y,B0.z,B0.w, B1.x,B1.y,B1.z,B1.w,
                        B2.x,B2.y,B2.z,B2.w, B3.x,B3.y,B3.z,B3.w};
        float Cv[16] = {C0.x,C0.y,C0.z,C0.w, C1.x,C1.y,C1.z,C1.w,
                        C2.x,C2.y,C2.z,C2.w, C3.x,C3.y,C3.z,C3.w};
        float y = xt * dpar;
#pragma unroll
        for (int s = 0; s < 16; s++) {
            float a = __expf(fminf(dt * Av[s], 10.f));
            float u = fminf(fmaxf(dt * Bv[s], -10.f), 10.f) * xt;
            float hv = fmaf(a, h[s], u);
            hv = fminf(fmaxf(hv, -10000.f), 10000.f);
            h[s] = hv;
            y = fmaf(hv, Cv[s], y);
        }
        g_ssm[base + (size_t)t * Dm] = y;
    }
}

// ---------------- router ----------------
__global__ void k_router(const float* __restrict__ Wr) {
    int gw = (blockIdx.x * blockDim.x + threadIdx.x) >> 5;
    int lane = threadIdx.x & 31;
    const float* xr = g_ssm + (size_t)gw * Dm;
    float a0 = 0, a1 = 0, a2 = 0, a3 = 0;
    for (int k = lane; k < Dm; k += 32) {
        float xv = xr[k];
        float4 w = *(const float4*)&Wr[k * 4];
        a0 = fmaf(xv, w.x, a0); a1 = fmaf(xv, w.y, a1);
        a2 = fmaf(xv, w.z, a2); a3 = fmaf(xv, w.w, a3);
    }
#pragma unroll
    for (int m = 16; m > 0; m >>= 1) {
        a0 += __shfl_xor_sync(~0u, a0, m);
        a1 += __shfl_xor_sync(~0u, a1, m);
        a2 += __shfl_xor_sync(~0u, a2, m);
        a3 += __shfl_xor_sync(~0u, a3, m);
    }
    if (lane == 0) {
        float l[4] = {a0, a1, a2, a3};
        float mx = fmaxf(fmaxf(l[0], l[1]), fmaxf(l[2], l[3]));
        float p[4]; float Z = 0.f;
#pragma unroll
        for (int q = 0; q < 4; q++) { p[q] = __expf(l[q] - mx); Z += p[q]; }
        float inv = 1.f / Z;
#pragma unroll
        for (int q = 0; q < 4; q++) p[q] *= inv;
        int i0 = 0;
#pragma unroll
        for (int q = 1; q < 4; q++) if (p[q] > p[i0]) i0 = q;
        int i1 = -1;
#pragma unroll
        for (int q = 0; q < 4; q++) if (q != i0 && (i1 < 0 || p[q] > p[i1])) i1 = q;
        float w0 = p[i0], w1 = p[i1];
        float den = w0 + w1 + 1e-9f;
        w0 /= den; w1 /= den;
        int pos0 = atomicAdd(&g_cnt[i0], 1);
        g_idx[i0 * TOK + pos0] = gw;
        int pos1 = atomicAdd(&g_cnt[i1], 1);
        g_idx[i1 * TOK + pos1] = gw;
        g_tokexp[2 * gw]     = i0; g_tokslot[2 * gw]     = pos0; g_tokw[2 * gw]     = w0;
        g_tokexp[2 * gw + 1] = i1; g_tokslot[2 * gw + 1] = pos1; g_tokw[2 * gw + 1] = w1;
    }
}

// ---------------- rmsnorm over hidden rows ----------------
__global__ void k_rmsg(const float* __restrict__ wn) {
    int e = blockIdx.y, i = blockIdx.x;
    if (i >= g_cnt[e]) return;
    float* row = g_hidden + ((size_t)e * TOK + i) * Hdim;
    __shared__ float red[8];
    int tid = threadIdx.x, lane = tid & 31, w = tid >> 5;
    float v[8];
    float ss = 0.f;
#pragma unroll
    for (int q = 0; q < 8; q++) { v[q] = row[tid + q * 256]; ss += v[q] * v[q]; }
#pragma unroll
    for (int m = 16; m > 0; m >>= 1) ss += __shfl_xor_sync(~0u, ss, m);
    if (lane == 0) red[w] = ss;
    __syncthreads();
    if (tid == 0) {
        float t = 0.f;
#pragma unroll
        for (int j = 0; j < 8; j++) t += red[j];
        red[0] = rsqrtf(t * (1.f / Hdim) + 1e-6f);
    }
    __syncthreads();
    float r = red[0];
#pragma unroll
    for (int q = 0; q < 8; q++) row[tid + q * 256] = wn[e * Hdim + tid + q * 256] * v[q] * r;
}

// ---------------- final ----------------
__global__ void k_final(const float* __restrict__ nw, float* __restrict__ out) {
    int n = blockIdx.x;
    int tid = threadIdx.x, lane = tid & 31, w = tid >> 5;
    __shared__ float red[8];
    const float* s = g_ssm + (size_t)n * Dm;
    int e0 = g_tokexp[2 * n], e1 = g_tokexp[2 * n + 1];
    int s0 = g_tokslot[2 * n], s1 = g_tokslot[2 * n + 1];
    float w0 = g_tokw[2 * n], w1 = g_tokw[2 * n + 1];
    const float* r0 = g_expout + ((size_t)e0 * TOK + s0) * Dm;
    const float* r1 = g_expout + ((size_t)e1 * TOK + s1) * Dm;
    float v[4];
    float ss = 0.f;
#pragma unroll
    for (int q = 0; q < 4; q++) {
        int i = tid + q * 256;
        float t = s[i] + w0 * r0[i] + w1 * r1[i];
        v[q] = t; ss += t * t;
    }
#pragma unroll
    for (int mm = 16; mm > 0; mm >>= 1) ss += __shfl_xor_sync(~0u, ss, mm);
    if (lane == 0) red[w] = ss;
    __syncthreads();
    if (tid == 0) {
        float t = 0.f;
#pragma unroll
        for (int j = 0; j < 8; j++) t += red[j];
        red[0] = rsqrtf(t * (1.f / Dm) + 1e-6f);
    }
    __syncthreads();
    float r = red[0];
#pragma unroll
    for (int q = 0; q < 4; q++)
        out[(size_t)n * Dm + tid + q * 256] = nw[tid + q * 256] * v[q] * r;
}

// ---------------- launch ----------------
extern "C" void kernel_launch(void* const* d_in, const int* in_sizes, int n_in,
                              void* d_out, int out_size) {
    const float* x        = (const float*)d_in[0];
    const float* A_log    = (const float*)d_in[1];
    const float* D_param  = (const float*)d_in[2];
    const float* W_delta  = (const float*)d_in[3];
    const float* b_delta  = (const float*)d_in[4];
    const float* W_B      = (const float*)d_in[5];
    const float* W_C      = (const float*)d_in[6];
    const float* W_router = (const float*)d_in[7];
    const float* Wg       = (const float*)d_in[8];
    const float* Wu       = (const float*)d_in[9];
    const float* Wd       = (const float*)d_in[10];
    const float* wn_exp   = (const float*)d_in[11];
    const float* norm_w   = (const float*)d_in[12];
    float* out = (float*)d_out;

    uint32_t *wg_h, *wg_l, *wu_h, *wu_l, *wd_h, *wd_l;
    cudaGetSymbolAddress((void**)&wg_h, g_WgP_h);
    cudaGetSymbolAddress((void**)&wg_l, g_WgP_l);
    cudaGetSymbolAddress((void**)&wu_h, g_WuP_h);
    cudaGetSymbolAddress((void**)&wu_l, g_WuP_l);
    cudaGetSymbolAddress((void**)&wd_h, g_WdP_h);
    cudaGetSymbolAddress((void**)&wd_l, g_WdP_l);

    k_init<<<1, 32>>>();
    k_prep<<<dim3(Hdim / 128, Dm / 32, Edim), 256>>>(Wg, wg_h, wg_l, Dm, Hdim);
    k_prep<<<dim3(Hdim / 128, Dm / 32, Edim), 256>>>(Wu, wu_h, wu_l, Dm, Hdim);
    k_prep<<<dim3(Dm / 128, Hdim / 32, Edim), 256>>>(Wd, wd_h, wd_l, Hdim, Dm);
    k_gemm0<<<dim3(Dm / 128, TOK / 128, 1), 256>>>(x, W_delta, b_delta);
    k_bc<<<TOK, 256>>>(x, W_B, W_C);
    k_scanA<<<dim3(Dm / 256, NCH, 2), 256>>>(x, A_log);
    k_scanB<<<(2 * Dm * Sdim) / 256, 256>>>();
    k_scanC<<<dim3(Dm / 256, NCH, 2), 256>>>(x, A_log, D_param);
    k_router<<<TOK / 8, 256>>>(W_router);
    k_moe<1><<<dim3(Hdim / 128, TOK / 128, Edim), 256>>>(wg_h, wg_l);
    k_moe<2><<<dim3(Hdim / 128, TOK / 128, Edim), 256>>>(wu_h, wu_l);
    k_rmsg<<<dim3(TOK, Edim), 256>>>(wn_exp);
    k_moe<3><<<dim3(Dm / 128, TOK / 128, Edim), 256>>>(wd_h, wd_l);
    k_final<<<TOK, 256>>>(norm_w, out);
}